// round 4
// baseline (speedup 1.0000x reference)
#include <cuda_runtime.h>
#include <cstdint>

// Skeleton forward kinematics: 6d rotations -> world-space joint positions.
// angles: [B, 16, 6] f32   xyz: [1, 16, 3] f32   out: [B, 16, 3] f32
//
// Round-4: persistent blocks, double-buffered cp.async pipeline over the
// round-3 tile design (pitch-129 float4 smem, pw flushed into consumed rows,
// coalesced gather). While tile i is computed from buffer A, tile i+1 streams
// gmem->smem into buffer B via LDGSTS (no register cost, no load stall).

namespace {

constexpr int NJ   = 16;
constexpr int TPB  = 128;
constexpr int PIT  = 129;                       // float4 pitch (odd -> conflict-free)
constexpr int BUF_F4 = 24 * PIT;                // float4s per buffer
constexpr size_t SMEM_BYTES = 2 * BUF_F4 * sizeof(float4) + 48 * sizeof(float);
constexpr int GRID = 304;                       // 2 per SM (152 SMs on GB300)

__device__ __forceinline__ void rot6d(const float* __restrict__ a, float R[9]) {
    float n1 = rsqrtf(a[0] * a[0] + a[1] * a[1] + a[2] * a[2]);
    float b1x = a[0] * n1, b1y = a[1] * n1, b1z = a[2] * n1;
    float d = b1x * a[3] + b1y * a[4] + b1z * a[5];
    float b2x = a[3] - d * b1x, b2y = a[4] - d * b1y, b2z = a[5] - d * b1z;
    float n2 = rsqrtf(b2x * b2x + b2y * b2y + b2z * b2z);
    b2x *= n2; b2y *= n2; b2z *= n2;
    R[0] = b1x; R[1] = b1y; R[2] = b1z;
    R[3] = b2x; R[4] = b2y; R[5] = b2z;
    R[6] = b1y * b2z - b1z * b2y;
    R[7] = b1z * b2x - b1x * b2z;
    R[8] = b1x * b2y - b1y * b2x;
}

__device__ __forceinline__ void stage_async(float4* __restrict__ buf,
                                            const float4* __restrict__ src,
                                            int t) {
#pragma unroll
    for (int k = 0; k < 24; ++k) {
        int g = t + k * TPB;                 // 0..3071
        int b = g / 24;
        int r = g - b * 24;
        uint32_t saddr = (uint32_t)__cvta_generic_to_shared(buf + r * PIT + b);
        asm volatile("cp.async.cg.shared.global [%0], [%1], 16;"
                     :: "r"(saddr), "l"(src + g) : "memory");
    }
    asm volatile("cp.async.commit_group;" ::: "memory");
}

// Compute FK for this thread's element (column t of buf); results left in buf
// as 12 float4 rows (pw), overwriting consumed angle rows.
__device__ __forceinline__ void compute_tile(float4* __restrict__ buf,
                                             const float* __restrict__ sref,
                                             int t) {
    float a2[12];
    float pw[48];
    float Rc[9], Rs[9];

    auto loadPair = [&](int j) {
        float4 q0 = buf[(3 * j + 0) * PIT + t];
        float4 q1 = buf[(3 * j + 1) * PIT + t];
        float4 q2 = buf[(3 * j + 2) * PIT + t];
        a2[0] = q0.x; a2[1] = q0.y; a2[2]  = q0.z; a2[3]  = q0.w;
        a2[4] = q1.x; a2[5] = q1.y; a2[6]  = q1.z; a2[7]  = q1.w;
        a2[8] = q2.x; a2[9] = q2.y; a2[10] = q2.z; a2[11] = q2.w;
    };
    auto flushRow = [&](int r) {
        buf[r * PIT + t] = make_float4(pw[4 * r + 0], pw[4 * r + 1],
                                       pw[4 * r + 2], pw[4 * r + 3]);
    };
    auto step = [&](int p, int c, int ao) {
        float R[9];
        rot6d(&a2[ao], R);
        float tx = sref[3 * c + 0] - sref[3 * p + 0];
        float ty = sref[3 * c + 1] - sref[3 * p + 1];
        float tz = sref[3 * c + 2] - sref[3 * p + 2];
        float ltx = R[0] * tx + R[1] * ty + R[2] * tz;
        float lty = R[3] * tx + R[4] * ty + R[5] * tz;
        float ltz = R[6] * tx + R[7] * ty + R[8] * tz;
        float Rn[9];
#pragma unroll
        for (int i = 0; i < 3; ++i)
#pragma unroll
            for (int k = 0; k < 3; ++k)
                Rn[3 * i + k] = Rc[3 * i + 0] * R[0 + k]
                              + Rc[3 * i + 1] * R[3 + k]
                              + Rc[3 * i + 2] * R[6 + k];
        pw[3 * c + 0] = Rc[0] * ltx + Rc[1] * lty + Rc[2] * ltz + pw[3 * p + 0];
        pw[3 * c + 1] = Rc[3] * ltx + Rc[4] * lty + Rc[5] * ltz + pw[3 * p + 1];
        pw[3 * c + 2] = Rc[6] * ltx + Rc[7] * lty + Rc[8] * ltz + pw[3 * p + 2];
#pragma unroll
        for (int i = 0; i < 9; ++i) Rc[i] = Rn[i];
    };

    // Root
    loadPair(0);
    rot6d(&a2[0], Rc);
    {
        float x = sref[0], y = sref[1], z = sref[2];
        pw[0] = Rc[0] * x + Rc[1] * y + Rc[2] * z;
        pw[1] = Rc[3] * x + Rc[4] * y + Rc[5] * z;
        pw[2] = Rc[6] * x + Rc[7] * y + Rc[8] * z;
    }

    // Chain 0-1-2-3 (flush row r only after all its angle floats consumed)
    step(0, 1, 6);  flushRow(0);
    loadPair(1);
    step(1, 2, 0);  flushRow(1);
    step(2, 3, 6);  flushRow(2);
#pragma unroll
    for (int i = 0; i < 9; ++i) Rs[i] = Rc[i];

    // Branch A: 3-4-5
    loadPair(2);
    step(3, 4, 0);
    step(4, 5, 6);  flushRow(3);

    // Branch B: 3-6-7-8-9-10
#pragma unroll
    for (int i = 0; i < 9; ++i) Rc[i] = Rs[i];
    loadPair(3);
    step(3, 6, 0);  flushRow(4);
    step(6, 7, 6);  flushRow(5);
    loadPair(4);
    step(7, 8, 0);
    step(8, 9, 6);  flushRow(6);
    loadPair(5);
    step(9, 10, 0); flushRow(7);

    // Branch C: 3-11-12-13-14-15
#pragma unroll
    for (int i = 0; i < 9; ++i) Rc[i] = Rs[i];
    step(3, 11, 6);  flushRow(8);
    loadPair(6);
    step(11, 12, 0);
    step(12, 13, 6); flushRow(9);
    loadPair(7);
    step(13, 14, 0); flushRow(10);
    step(14, 15, 6); flushRow(11);
}

__global__ __launch_bounds__(TPB)
void skeleton_fk_v4(const float4* __restrict__ angles4,
                    const float*  __restrict__ xyz,
                    float4* __restrict__ out4,
                    int numTiles)
{
    extern __shared__ float4 smem[];
    float4* bufs[2] = { smem, smem + BUF_F4 };
    float* sref = reinterpret_cast<float*>(smem + 2 * BUF_F4);

    const int t = threadIdx.x;
    if (t < 48) sref[t] = __ldg(xyz + t);

    int tile = blockIdx.x;
    const int stride = gridDim.x;
    if (tile >= numTiles) return;

    // Prologue: stage first tile into buffer 0.
    stage_async(bufs[0], angles4 + (size_t)tile * (TPB * 24), t);

    int cur = 0;
    while (tile < numTiles) {
        const int next = tile + stride;
        if (next < numTiles) {
            stage_async(bufs[cur ^ 1], angles4 + (size_t)next * (TPB * 24), t);
            asm volatile("cp.async.wait_group 1;" ::: "memory");
        } else {
            asm volatile("cp.async.wait_group 0;" ::: "memory");
        }
        __syncthreads();                       // tile data (and sref) visible

        compute_tile(bufs[cur], sref, t);
        __syncthreads();                       // pw rows visible to gatherers

        float4* __restrict__ dst = out4 + (size_t)tile * (TPB * 12);
        float4* __restrict__ buf = bufs[cur];
#pragma unroll
        for (int k = 0; k < 12; ++k) {
            int g = t + k * TPB;               // 0..1535
            int b = g / 12;
            int r = g - b * 12;
            dst[g] = buf[r * PIT + b];
        }
        __syncthreads();                       // buffer free for reuse (iter+2)

        cur ^= 1;
        tile = next;
    }
}

// Tail fallback (batch not a multiple of TPB; unused for BATCH=262144).
__global__ void skeleton_fk_tail(const float* __restrict__ angles,
                                 const float* __restrict__ xyz,
                                 float* __restrict__ out,
                                 int start, int batch)
{
    int b = start + blockIdx.x * blockDim.x + threadIdx.x;
    if (b >= batch) return;
    const float* ab = angles + (size_t)b * (NJ * 6);
    float ref[NJ * 3];
#pragma unroll
    for (int i = 0; i < NJ * 3; ++i) ref[i] = __ldg(xyz + i);

    float Rw[NJ * 9], pw[NJ * 3];
    {
        float a[6];
#pragma unroll
        for (int k = 0; k < 6; ++k) a[k] = ab[k];
        rot6d(a, &Rw[0]);
        float x = ref[0], y = ref[1], z = ref[2];
        pw[0] = Rw[0] * x + Rw[1] * y + Rw[2] * z;
        pw[1] = Rw[3] * x + Rw[4] * y + Rw[5] * z;
        pw[2] = Rw[6] * x + Rw[7] * y + Rw[8] * z;
    }
    constexpr int PARENT[15] = {0, 1, 2, 3, 4, 3, 6, 7, 8, 9, 3, 11, 12, 13, 14};
#pragma unroll
    for (int e = 0; e < 15; ++e) {
        const int p = PARENT[e], c = e + 1;
        float a[6];
#pragma unroll
        for (int k = 0; k < 6; ++k) a[k] = ab[6 * c + k];
        float R[9]; rot6d(a, R);
        float tx = ref[3 * c + 0] - ref[3 * p + 0];
        float ty = ref[3 * c + 1] - ref[3 * p + 1];
        float tz = ref[3 * c + 2] - ref[3 * p + 2];
        float ltx = R[0] * tx + R[1] * ty + R[2] * tz;
        float lty = R[3] * tx + R[4] * ty + R[5] * tz;
        float ltz = R[6] * tx + R[7] * ty + R[8] * tz;
        const float* pR = &Rw[9 * p];
        float* nR = &Rw[9 * c];
#pragma unroll
        for (int i = 0; i < 3; ++i)
#pragma unroll
            for (int k = 0; k < 3; ++k)
                nR[3 * i + k] = pR[3 * i + 0] * R[k] + pR[3 * i + 1] * R[3 + k]
                              + pR[3 * i + 2] * R[6 + k];
        pw[3 * c + 0] = pR[0] * ltx + pR[1] * lty + pR[2] * ltz + pw[3 * p + 0];
        pw[3 * c + 1] = pR[3] * ltx + pR[4] * lty + pR[5] * ltz + pw[3 * p + 1];
        pw[3 * c + 2] = pR[6] * ltx + pR[7] * lty + pR[8] * ltz + pw[3 * p + 2];
    }
    float* o = out + (size_t)b * (NJ * 3);
#pragma unroll
    for (int i = 0; i < NJ * 3; ++i) o[i] = pw[i];
}

}  // namespace

extern "C" void kernel_launch(void* const* d_in, const int* in_sizes, int n_in,
                              void* d_out, int out_size) {
    const float* angles = (const float*)d_in[0];
    const float* xyz    = (const float*)d_in[1];
    float* out          = (float*)d_out;

    const int batch    = in_sizes[0] / (NJ * 6);
    const int numTiles = batch / TPB;

    cudaFuncSetAttribute(skeleton_fk_v4,
                         cudaFuncAttributeMaxDynamicSharedMemorySize,
                         (int)SMEM_BYTES);

    if (numTiles > 0) {
        int grid = numTiles < GRID ? numTiles : GRID;
        skeleton_fk_v4<<<grid, TPB, SMEM_BYTES>>>(
            (const float4*)angles, xyz, (float4*)out, numTiles);
    }
    const int rem = batch - numTiles * TPB;
    if (rem > 0) {
        skeleton_fk_tail<<<(rem + 127) / 128, 128>>>(angles, xyz, out,
                                                     numTiles * TPB, batch);
    }
}

// round 5
// speedup vs baseline: 1.1948x; 1.1948x over previous
#include <cuda_runtime.h>
#include <cstdint>

// Skeleton forward kinematics: 6d rotations -> world-space joint positions.
// angles: [B, 16, 6] f32   xyz: [1, 16, 3] f32   out: [B, 16, 3] f32
//
// Round-5: warp-autonomous tiles. Each warp owns a private smem strip of
// 32 batch elements ([24 rows][33 cols] float4, conflict-free odd pitch) and
// runs stage (cp.async) -> compute -> gather with only __syncwarp between
// phases. No block-wide barriers: every warp is an independent pipeline.

namespace {

constexpr int NJ    = 16;
constexpr int WPB   = 3;                 // warps per block
constexpr int TPB   = 32 * WPB;          // 96 threads
constexpr int WPIT  = 33;                // per-warp float4 pitch (odd)
constexpr int STRIP = 24 * WPIT;         // float4s per warp strip
constexpr size_t SMEM_BYTES =
    (size_t)WPB * STRIP * sizeof(float4) + (size_t)WPB * 48 * sizeof(float);

__device__ __forceinline__ void rot6d(const float* __restrict__ a, float R[9]) {
    float n1 = rsqrtf(a[0] * a[0] + a[1] * a[1] + a[2] * a[2]);
    float b1x = a[0] * n1, b1y = a[1] * n1, b1z = a[2] * n1;
    float d = b1x * a[3] + b1y * a[4] + b1z * a[5];
    float b2x = a[3] - d * b1x, b2y = a[4] - d * b1y, b2z = a[5] - d * b1z;
    float n2 = rsqrtf(b2x * b2x + b2y * b2y + b2z * b2z);
    b2x *= n2; b2y *= n2; b2z *= n2;
    R[0] = b1x; R[1] = b1y; R[2] = b1z;
    R[3] = b2x; R[4] = b2y; R[5] = b2z;
    R[6] = b1y * b2z - b1z * b2y;
    R[7] = b1z * b2x - b1x * b2z;
    R[8] = b1x * b2y - b1y * b2x;
}

__global__ __launch_bounds__(TPB)
void skeleton_fk_v5(const float4* __restrict__ angles4,
                    const float*  __restrict__ xyz,
                    float4* __restrict__ out4,
                    int numWarpTiles)
{
    extern __shared__ float4 smem[];
    const int l = threadIdx.x & 31;
    const int w = threadIdx.x >> 5;

    const int wt = blockIdx.x * WPB + w;       // global warp-tile id
    if (wt >= numWarpTiles) return;            // safe: no block barriers

    float4* __restrict__ strip = smem + w * STRIP;
    float*  __restrict__ sref  =
        reinterpret_cast<float*>(smem + WPB * STRIP) + w * 48;

    const size_t eBase = (size_t)wt * 32;      // first batch element of tile

    // ---- Stage: coalesced cp.async into transposed strip ----
    const float4* __restrict__ src = angles4 + eBase * 24;
#pragma unroll
    for (int k = 0; k < 24; ++k) {
        int g = l + k * 32;                    // 0..767
        int b = g / 24;
        int r = g - b * 24;
        uint32_t saddr = (uint32_t)__cvta_generic_to_shared(strip + r * WPIT + b);
        asm volatile("cp.async.cg.shared.global [%0], [%1], 16;"
                     :: "r"(saddr), "l"(src + g) : "memory");
    }
    asm volatile("cp.async.commit_group;" ::: "memory");

    // Per-warp reference copy (warp-private, no cross-warp races).
    if (l < 16) {
        sref[l]      = __ldg(xyz + l);
        sref[l + 16] = __ldg(xyz + l + 16);
        sref[l + 32] = __ldg(xyz + l + 32);
    }

    asm volatile("cp.async.wait_group 0;" ::: "memory");
    __syncwarp();

    // ---- Compute (identical FK to v3; pw flushed into consumed rows) ----
    {
        float a2[12];
        float pw[48];
        float Rc[9], Rs[9];

        auto loadPair = [&](int j) {
            float4 q0 = strip[(3 * j + 0) * WPIT + l];
            float4 q1 = strip[(3 * j + 1) * WPIT + l];
            float4 q2 = strip[(3 * j + 2) * WPIT + l];
            a2[0] = q0.x; a2[1] = q0.y; a2[2]  = q0.z; a2[3]  = q0.w;
            a2[4] = q1.x; a2[5] = q1.y; a2[6]  = q1.z; a2[7]  = q1.w;
            a2[8] = q2.x; a2[9] = q2.y; a2[10] = q2.z; a2[11] = q2.w;
        };
        auto flushRow = [&](int r) {
            strip[r * WPIT + l] = make_float4(pw[4 * r + 0], pw[4 * r + 1],
                                              pw[4 * r + 2], pw[4 * r + 3]);
        };
        auto step = [&](int p, int c, int ao) {
            float R[9];
            rot6d(&a2[ao], R);
            float tx = sref[3 * c + 0] - sref[3 * p + 0];
            float ty = sref[3 * c + 1] - sref[3 * p + 1];
            float tz = sref[3 * c + 2] - sref[3 * p + 2];
            float ltx = R[0] * tx + R[1] * ty + R[2] * tz;
            float lty = R[3] * tx + R[4] * ty + R[5] * tz;
            float ltz = R[6] * tx + R[7] * ty + R[8] * tz;
            float Rn[9];
#pragma unroll
            for (int i = 0; i < 3; ++i)
#pragma unroll
                for (int k = 0; k < 3; ++k)
                    Rn[3 * i + k] = Rc[3 * i + 0] * R[0 + k]
                                  + Rc[3 * i + 1] * R[3 + k]
                                  + Rc[3 * i + 2] * R[6 + k];
            pw[3 * c + 0] = Rc[0] * ltx + Rc[1] * lty + Rc[2] * ltz + pw[3 * p + 0];
            pw[3 * c + 1] = Rc[3] * ltx + Rc[4] * lty + Rc[5] * ltz + pw[3 * p + 1];
            pw[3 * c + 2] = Rc[6] * ltx + Rc[7] * lty + Rc[8] * ltz + pw[3 * p + 2];
#pragma unroll
            for (int i = 0; i < 9; ++i) Rc[i] = Rn[i];
        };

        // Root joint 0
        loadPair(0);
        rot6d(&a2[0], Rc);
        {
            float x = sref[0], y = sref[1], z = sref[2];
            pw[0] = Rc[0] * x + Rc[1] * y + Rc[2] * z;
            pw[1] = Rc[3] * x + Rc[4] * y + Rc[5] * z;
            pw[2] = Rc[6] * x + Rc[7] * y + Rc[8] * z;
        }

        // Chain 0-1-2-3 (flush row r only after its angle floats consumed)
        step(0, 1, 6);  flushRow(0);
        loadPair(1);
        step(1, 2, 0);  flushRow(1);
        step(2, 3, 6);  flushRow(2);
#pragma unroll
        for (int i = 0; i < 9; ++i) Rs[i] = Rc[i];

        // Branch A: 3-4-5
        loadPair(2);
        step(3, 4, 0);
        step(4, 5, 6);  flushRow(3);

        // Branch B: 3-6-7-8-9-10
#pragma unroll
        for (int i = 0; i < 9; ++i) Rc[i] = Rs[i];
        loadPair(3);
        step(3, 6, 0);  flushRow(4);
        step(6, 7, 6);  flushRow(5);
        loadPair(4);
        step(7, 8, 0);
        step(8, 9, 6);  flushRow(6);
        loadPair(5);
        step(9, 10, 0); flushRow(7);

        // Branch C: 3-11-12-13-14-15
#pragma unroll
        for (int i = 0; i < 9; ++i) Rc[i] = Rs[i];
        step(3, 11, 6);  flushRow(8);
        loadPair(6);
        step(11, 12, 0);
        step(12, 13, 6); flushRow(9);
        loadPair(7);
        step(13, 14, 0); flushRow(10);
        step(14, 15, 6); flushRow(11);
    }

    __syncwarp();

    // ---- Gather: conflict-free LDS.128 -> coalesced STG.128 ----
    float4* __restrict__ dst = out4 + eBase * 12;
#pragma unroll
    for (int k = 0; k < 12; ++k) {
        int g = l + k * 32;                    // 0..383
        int b = g / 12;
        int r = g - b * 12;
        dst[g] = strip[r * WPIT + b];
    }
}

// Tail fallback for batch % 32 != 0 (unused for BATCH=262144).
__global__ void skeleton_fk_tail(const float* __restrict__ angles,
                                 const float* __restrict__ xyz,
                                 float* __restrict__ out,
                                 int start, int batch)
{
    int b = start + blockIdx.x * blockDim.x + threadIdx.x;
    if (b >= batch) return;
    const float* ab = angles + (size_t)b * (NJ * 6);
    float ref[NJ * 3];
#pragma unroll
    for (int i = 0; i < NJ * 3; ++i) ref[i] = __ldg(xyz + i);

    float Rw[NJ * 9], pw[NJ * 3];
    {
        float a[6];
#pragma unroll
        for (int k = 0; k < 6; ++k) a[k] = ab[k];
        rot6d(a, &Rw[0]);
        float x = ref[0], y = ref[1], z = ref[2];
        pw[0] = Rw[0] * x + Rw[1] * y + Rw[2] * z;
        pw[1] = Rw[3] * x + Rw[4] * y + Rw[5] * z;
        pw[2] = Rw[6] * x + Rw[7] * y + Rw[8] * z;
    }
    constexpr int PARENT[15] = {0, 1, 2, 3, 4, 3, 6, 7, 8, 9, 3, 11, 12, 13, 14};
#pragma unroll
    for (int e = 0; e < 15; ++e) {
        const int p = PARENT[e], c = e + 1;
        float a[6];
#pragma unroll
        for (int k = 0; k < 6; ++k) a[k] = ab[6 * c + k];
        float R[9]; rot6d(a, R);
        float tx = ref[3 * c + 0] - ref[3 * p + 0];
        float ty = ref[3 * c + 1] - ref[3 * p + 1];
        float tz = ref[3 * c + 2] - ref[3 * p + 2];
        float ltx = R[0] * tx + R[1] * ty + R[2] * tz;
        float lty = R[3] * tx + R[4] * ty + R[5] * tz;
        float ltz = R[6] * tx + R[7] * ty + R[8] * tz;
        const float* pR = &Rw[9 * p];
        float* nR = &Rw[9 * c];
#pragma unroll
        for (int i = 0; i < 3; ++i)
#pragma unroll
            for (int k = 0; k < 3; ++k)
                nR[3 * i + k] = pR[3 * i + 0] * R[k] + pR[3 * i + 1] * R[3 + k]
                              + pR[3 * i + 2] * R[6 + k];
        pw[3 * c + 0] = pR[0] * ltx + pR[1] * lty + pR[2] * ltz + pw[3 * p + 0];
        pw[3 * c + 1] = pR[3] * ltx + pR[4] * lty + pR[5] * ltz + pw[3 * p + 1];
        pw[3 * c + 2] = pR[6] * ltx + pR[7] * lty + pR[8] * ltz + pw[3 * p + 2];
    }
    float* o = out + (size_t)b * (NJ * 3);
#pragma unroll
    for (int i = 0; i < NJ * 3; ++i) o[i] = pw[i];
}

}  // namespace

extern "C" void kernel_launch(void* const* d_in, const int* in_sizes, int n_in,
                              void* d_out, int out_size) {
    const float* angles = (const float*)d_in[0];
    const float* xyz    = (const float*)d_in[1];
    float* out          = (float*)d_out;

    const int batch        = in_sizes[0] / (NJ * 6);
    const int numWarpTiles = batch / 32;
    const int blocks       = (numWarpTiles + WPB - 1) / WPB;

    cudaFuncSetAttribute(skeleton_fk_v5,
                         cudaFuncAttributeMaxDynamicSharedMemorySize,
                         (int)SMEM_BYTES);

    if (blocks > 0) {
        skeleton_fk_v5<<<blocks, TPB, SMEM_BYTES>>>(
            (const float4*)angles, xyz, (float4*)out, numWarpTiles);
    }
    const int rem = batch - numWarpTiles * 32;
    if (rem > 0) {
        skeleton_fk_tail<<<(rem + 127) / 128, 128>>>(angles, xyz, out,
                                                     numWarpTiles * 32, batch);
    }
}